// round 2
// baseline (speedup 1.0000x reference)
#include <cuda_runtime.h>
#include <math.h>

#define BB 4
#define CC 64
#define LL 4096
#define CQ 16
#define NH 4
#define NBK 32
#define TILE 512

// ---------------- scratch (device globals; no allocation allowed) ----------------
__device__ float g_qT[BB * LL * CQ];                 // (b, l, cq)
__device__ float g_kT[BB * LL * CQ];                 // (b, l, cq)
__device__ float g_vT[BB * LL * CC];                 // (b, l, c)
__device__ int   g_sidx[BB * NH * LL];               // sorted member lists per (b,h)
__device__ int   g_boff[BB * NH * (NBK + 1)];        // bucket offsets per (b,h)
__device__ float g_accH[(size_t)BB * NH * LL * CC];  // per-hash attention output (b,h,l,c)
__device__ float g_part[128 * CC];                   // BN partial sums
__device__ float g_psq[128 * CC];                    // BN partial sum of squares
__device__ float g_stats[2 * CC];                    // per-channel scale / shift

// ---------------- K1: fused q/k/v 1x1 convs ----------------
// grid (LL/128, BB), block 128. Thread t handles position l0+t.
__global__ void __launch_bounds__(128) k_qkv(
    const float* __restrict__ x,
    const float* __restrict__ Wq, const float* __restrict__ bq,
    const float* __restrict__ Wk, const float* __restrict__ bk,
    const float* __restrict__ Wv, const float* __restrict__ bv)
{
    __shared__ float WqS[CQ * CC], WkS[CQ * CC], WvS[CC * CC];
    __shared__ float bqS[CQ], bkS[CQ], bvS[CC];
    __shared__ float outS[128 * 17];

    const int t  = threadIdx.x;
    const int l0 = blockIdx.x * 128;
    const int b  = blockIdx.y;

    for (int e = t; e < CQ * CC; e += 128) { WqS[e] = Wq[e]; WkS[e] = Wk[e]; }
    for (int e = t; e < CC * CC; e += 128) WvS[e] = Wv[e];
    if (t < CQ) { bqS[t] = bq[t]; bkS[t] = bk[t]; }
    if (t < CC) bvS[t] = bv[t];
    __syncthreads();

    const float* xb = x + (size_t)b * CC * LL + l0 + t;

    // 6 passes of 16 output channels each: q(16), k(16), v(4x16).
    for (int pass = 0; pass < 6; pass++) {
        const float* W;
        const float* bias;
        if (pass == 0)      { W = WqS; bias = bqS; }
        else if (pass == 1) { W = WkS; bias = bkS; }
        else                { W = WvS + (pass - 2) * 16 * CC; bias = bvS + (pass - 2) * 16; }

        float r[16];
        #pragma unroll
        for (int o = 0; o < 16; o++) r[o] = bias[o];

        for (int c = 0; c < CC; c++) {
            float xv = __ldg(xb + (size_t)c * LL);
            #pragma unroll
            for (int o = 0; o < 16; o++) r[o] += W[o * CC + c] * xv;
        }

        __syncthreads();  // previous dump done before reusing outS
        #pragma unroll
        for (int o = 0; o < 16; o++) outS[t * 17 + o] = r[o];
        __syncthreads();

        if (pass == 0) {
            float* dst = g_qT + ((size_t)b * LL + l0) * CQ;
            for (int e = t; e < 128 * 16; e += 128) dst[e] = outS[(e >> 4) * 17 + (e & 15)];
        } else if (pass == 1) {
            float* dst = g_kT + ((size_t)b * LL + l0) * CQ;
            for (int e = t; e < 128 * 16; e += 128) dst[e] = outS[(e >> 4) * 17 + (e & 15)];
        } else {
            float* dst = g_vT + ((size_t)b * LL + l0) * CC + (pass - 2) * 16;
            for (int e = t; e < 128 * 16; e += 128) {
                int p = e >> 4, o = e & 15;
                dst[(size_t)p * CC + o] = outS[p * 17 + o];
            }
        }
    }
}

// ---------------- K2: deterministic stable counting sort per (b,h) ----------------
// grid BB*NH, block 256, each thread owns 16 consecutive positions.
__global__ void __launch_bounds__(256) k_sort(const int* __restrict__ hash_idx)
{
    __shared__ int cnt[256 * 33];
    __shared__ int tot[NBK];
    __shared__ int bbase[NBK];

    const int t  = threadIdx.x;
    const int bh = blockIdx.x;
    const int* hp = hash_idx + (size_t)bh * LL;

    #pragma unroll
    for (int u = 0; u < 33; u++) cnt[t * 33 + u] = 0;

    const int l0 = t * 16;
    int loc[16];
    #pragma unroll
    for (int i = 0; i < 16; i++) {
        int bu = hp[l0 + i];
        loc[i] = bu;
        cnt[t * 33 + bu]++;
    }
    __syncthreads();

    if (t < NBK) {
        int run = 0;
        for (int j = 0; j < 256; j++) {
            int v = cnt[j * 33 + t];
            cnt[j * 33 + t] = run;
            run += v;
        }
        tot[t] = run;
    }
    __syncthreads();

    if (t == 0) {
        int running = 0;
        for (int u = 0; u < NBK; u++) {
            bbase[u] = running;
            g_boff[bh * (NBK + 1) + u] = running;
            running += tot[u];
        }
        g_boff[bh * (NBK + 1) + NBK] = running;  // == LL
    }
    __syncthreads();

    int* sp = g_sidx + (size_t)bh * LL;
    #pragma unroll
    for (int i = 0; i < 16; i++) {
        int bu = loc[i];
        int pos = bbase[bu] + cnt[t * 33 + bu];
        cnt[t * 33 + bu]++;
        sp[pos] = l0 + i;
    }
}

// ---------------- K3: per-bucket flash attention ----------------
__device__ __forceinline__ void load_tile(const int* __restrict__ sp,
                                          const float* __restrict__ kTb,
                                          int t0, int tn, int t,
                                          float* Ks, int* poss)
{
    for (int e = t; e < tn; e += 256) poss[e] = sp[t0 + e];
    __syncthreads();
    for (int e = t; e < tn * CQ; e += 256) {
        int j = e >> 4, c = e & 15;
        Ks[c * (TILE + 1) + j] = kTb[(size_t)poss[j] * CQ + c];
    }
}

__device__ __forceinline__ void flash_tile(const float* __restrict__ Ks,
                                           const int* __restrict__ poss,
                                           const float* __restrict__ vTb,
                                           const float q[16], int tn, int lane,
                                           float& m, float& l, float& ax, float& ay)
{
    for (int jj = 0; jj < tn; jj += 32) {
        int j = jj + lane;
        float s = -3.0e38f;
        if (j < tn) {
            float acc = 0.f;
            #pragma unroll
            for (int c = 0; c < CQ; c++) acc += q[c] * Ks[c * (TILE + 1) + j];
            s = acc;
        }
        float smax = s;
        #pragma unroll
        for (int o = 16; o; o >>= 1) smax = fmaxf(smax, __shfl_xor_sync(0xffffffffu, smax, o));
        float mnew = fmaxf(m, smax);
        float p = (j < tn) ? __expf(s - mnew) : 0.f;
        float ps = p;
        #pragma unroll
        for (int o = 16; o; o >>= 1) ps += __shfl_xor_sync(0xffffffffu, ps, o);
        float corr = __expf(m - mnew);  // m starts at -3e38 -> corr == 0 on first tile
        l = l * corr + ps;
        ax *= corr; ay *= corr;
        m = mnew;

        int cm = min(32, tn - jj);
        #pragma unroll 4
        for (int u = 0; u < cm; u++) {
            float pu = __shfl_sync(0xffffffffu, p, u);
            int pos = poss[jj + u];
            float2 v = *(const float2*)(vTb + (size_t)pos * CC + 2 * lane);
            ax += pu * v.x;
            ay += pu * v.y;
        }
    }
}

// grid (NBK, NH, BB), block 256 (8 warps, warp per query)
__global__ void __launch_bounds__(256) k_attn()
{
    __shared__ float Ks[CQ * (TILE + 1)];
    __shared__ int poss[TILE];

    const int bu = blockIdx.x, h = blockIdx.y, b = blockIdx.z;
    const int bh = b * NH + h;
    const int base = g_boff[bh * (NBK + 1) + bu];
    const int n    = g_boff[bh * (NBK + 1) + bu + 1] - base;
    if (n <= 0) return;

    const int*   sp  = g_sidx + (size_t)bh * LL + base;
    const float* kTb = g_kT + (size_t)b * LL * CQ;
    const float* qTb = g_qT + (size_t)b * LL * CQ;
    const float* vTb = g_vT + (size_t)b * LL * CC;
    float*       op  = g_accH + (size_t)bh * LL * CC;

    const int t = threadIdx.x, wid = t >> 5, lane = t & 31;

    if (n <= TILE) {
        // fast path: whole bucket fits one smem tile (realistic data: n ~ 128)
        load_tile(sp, kTb, 0, n, t, Ks, poss);
        __syncthreads();
        for (int qi = wid; qi < n; qi += 8) {
            int qpos = poss[qi];
            float q[16];
            const float4* qp = (const float4*)(qTb + (size_t)qpos * CQ);
            #pragma unroll
            for (int c4 = 0; c4 < 4; c4++) {
                float4 v = __ldg(qp + c4);
                q[c4 * 4 + 0] = v.x; q[c4 * 4 + 1] = v.y;
                q[c4 * 4 + 2] = v.z; q[c4 * 4 + 3] = v.w;
            }
            float m = -3.0e38f, l = 0.f, ax = 0.f, ay = 0.f;
            flash_tile(Ks, poss, vTb, q, n, lane, m, l, ax, ay);
            float inv = 1.0f / l;
            *(float2*)(op + (size_t)qpos * CC + 2 * lane) = make_float2(ax * inv, ay * inv);
        }
    } else {
        // general path: tiled online softmax (correct for any bucket size)
        for (int qc = 0; qc < n; qc += 8) {
            int qi = qc + wid;
            bool valid = qi < n;
            int qpos = valid ? sp[qi] : sp[0];
            float q[16];
            const float4* qp = (const float4*)(qTb + (size_t)qpos * CQ);
            #pragma unroll
            for (int c4 = 0; c4 < 4; c4++) {
                float4 v = __ldg(qp + c4);
                q[c4 * 4 + 0] = v.x; q[c4 * 4 + 1] = v.y;
                q[c4 * 4 + 2] = v.z; q[c4 * 4 + 3] = v.w;
            }
            float m = -3.0e38f, l = 0.f, ax = 0.f, ay = 0.f;
            for (int t0 = 0; t0 < n; t0 += TILE) {
                int tn = min(TILE, n - t0);
                __syncthreads();
                load_tile(sp, kTb, t0, tn, t, Ks, poss);
                __syncthreads();
                flash_tile(Ks, poss, vTb, q, tn, lane, m, l, ax, ay);
            }
            if (valid) {
                float inv = 1.0f / l;
                *(float2*)(op + (size_t)qpos * CC + 2 * lane) = make_float2(ax * inv, ay * inv);
            }
        }
    }
}

// ---------------- K4: hash-average + Wo conv + residual + BN partials ----------------
// grid (LL/128, BB), block 512 = (16 channel-groups x 32 pos-groups), 4x4 reg tile.
// dynamic smem: WoS (4096) + attnS (64*132) floats = 50176 bytes
__global__ void __launch_bounds__(512) k_out(
    const float* __restrict__ x,
    const float* __restrict__ Wo, const float* __restrict__ bo,
    const float* __restrict__ gamma, float* __restrict__ out)
{
    extern __shared__ float sm[];
    float* WoS   = sm;          // 64*64
    float* attnS = sm + 4096;   // [c][pos], stride 132 (float4-aligned, conflict-free)

    const int t  = threadIdx.x;
    const int l0 = blockIdx.x * 128;
    const int b  = blockIdx.y;

    for (int e = t; e < CC * CC; e += 512) WoS[e] = Wo[e];

    const float* ab = g_accH + (size_t)b * NH * LL * CC + (size_t)l0 * CC;  // h=0
    const size_t hstr = (size_t)LL * CC;
    for (int e = t; e < 128 * CC; e += 512) {
        int pos = e >> 6, c = e & 63;
        size_t off = (size_t)pos * CC + c;
        float s = ab[off] + ab[off + hstr] + ab[off + 2 * hstr] + ab[off + 3 * hstr];
        attnS[c * 132 + pos] = 0.25f * s;
    }
    __syncthreads();

    const int ct = t >> 5, pt = t & 31, c0 = ct * 4;
    float acc[4][4];
    #pragma unroll
    for (int i = 0; i < 4; i++) {
        float bi = __ldg(bo + c0 + i);
        #pragma unroll
        for (int j = 0; j < 4; j++) acc[i][j] = bi;
    }

    for (int cp = 0; cp < CC; cp++) {
        float4 av = *(const float4*)&attnS[cp * 132 + pt * 4];
        #pragma unroll
        for (int i = 0; i < 4; i++) {
            float w = WoS[(c0 + i) * CC + cp];
            acc[i][0] += w * av.x; acc[i][1] += w * av.y;
            acc[i][2] += w * av.z; acc[i][3] += w * av.w;
        }
    }

    const float g = __ldg(gamma);
    const int blk = b * gridDim.x + blockIdx.x;

    #pragma unroll
    for (int i = 0; i < 4; i++) {
        int c = c0 + i;
        size_t gbase = ((size_t)b * CC + c) * LL + l0 + pt * 4;
        float4 xv = *(const float4*)(x + gbase);
        float4 y;
        y.x = g * acc[i][0] + xv.x;
        y.y = g * acc[i][1] + xv.y;
        y.z = g * acc[i][2] + xv.z;
        y.w = g * acc[i][3] + xv.w;
        *(float4*)(out + gbase) = y;

        float s1 = y.x + y.y + y.z + y.w;
        float s2 = y.x * y.x + y.y * y.y + y.z * y.z + y.w * y.w;
        #pragma unroll
        for (int o = 16; o; o >>= 1) {
            s1 += __shfl_xor_sync(0xffffffffu, s1, o);
            s2 += __shfl_xor_sync(0xffffffffu, s2, o);
        }
        if (pt == 0) { g_part[blk * CC + c] = s1; g_psq[blk * CC + c] = s2; }
    }
}

// ---------------- K5: BN stats reduce (deterministic, double accum) ----------------
__global__ void k_stats(const float* __restrict__ bn_w, const float* __restrict__ bn_b)
{
    int c = threadIdx.x;  // 64 threads
    double s1 = 0.0, s2 = 0.0;
    for (int i = 0; i < 128; i++) { s1 += g_part[i * CC + c]; s2 += g_psq[i * CC + c]; }
    const double n = (double)BB * (double)LL;
    double mean = s1 / n;
    double var  = s2 / n - mean * mean;
    double a    = (double)bn_w[c] / sqrt(var + 1e-5);
    g_stats[c]      = (float)a;
    g_stats[CC + c] = (float)((double)bn_b[c] - mean * a);
}

// ---------------- K6: normalize in place ----------------
__global__ void __launch_bounds__(256) k_norm(float* __restrict__ out)
{
    int i = blockIdx.x * 256 + threadIdx.x;  // float4 index
    int c = (i >> 10) & 63;                  // (4i / L) % 64
    float a = g_stats[c], sh = g_stats[CC + c];
    float4* p = (float4*)out;
    float4 v = p[i];
    v.x = v.x * a + sh; v.y = v.y * a + sh;
    v.z = v.z * a + sh; v.w = v.w * a + sh;
    p[i] = v;
}

// ---------------- launch ----------------
extern "C" void kernel_launch(void* const* d_in, const int* in_sizes, int n_in,
                              void* d_out, int out_size)
{
    const float* x     = (const float*)d_in[0];
    const int*   hashi = (const int*)  d_in[1];
    const float* Wq    = (const float*)d_in[2];
    const float* bq    = (const float*)d_in[3];
    const float* Wk    = (const float*)d_in[4];
    const float* bk    = (const float*)d_in[5];
    const float* Wv    = (const float*)d_in[6];
    const float* bv    = (const float*)d_in[7];
    const float* Wo    = (const float*)d_in[8];
    const float* bo    = (const float*)d_in[9];
    const float* gamma = (const float*)d_in[10];
    const float* bn_w  = (const float*)d_in[11];
    const float* bn_b  = (const float*)d_in[12];
    float* out = (float*)d_out;

    cudaFuncSetAttribute(k_out, cudaFuncAttributeMaxDynamicSharedMemorySize, 65536);

    k_qkv<<<dim3(LL / 128, BB), 128>>>(x, Wq, bq, Wk, bk, Wv, bv);
    k_sort<<<BB * NH, 256>>>(hashi);
    k_attn<<<dim3(NBK, NH, BB), 256>>>();
    k_out<<<dim3(LL / 128, BB), 512, 50176>>>(x, Wo, bo, gamma, out);
    k_stats<<<1, 64>>>(bn_w, bn_b);
    k_norm<<<(BB * CC * LL / 4) / 256, 256>>>(out);
}

// round 6
// speedup vs baseline: 2.2858x; 2.2858x over previous
#include <cuda_runtime.h>
#include <math.h>

#define BB 4
#define CC 64
#define LL 4096
#define CQ 16
#define NH 4
#define NBK 32

// ---------------- scratch (device globals; no allocation allowed) ----------------
__device__ float g_qT[BB * LL * CQ];                 // (b, l, cq)
__device__ float g_kT[BB * LL * CQ];                 // (b, l, cq)
__device__ float g_vT[BB * LL * CC];                 // (b, l, c)
__device__ int   g_sidx[BB * NH * LL];               // sorted member lists per (b,h)
__device__ int   g_boff[BB * NH * (NBK + 1)];        // bucket offsets per (b,h)
__device__ float g_accH[(size_t)BB * NH * LL * CC];  // per-hash attention output (b,h,l,c)
__device__ float g_part[128 * CC];                   // BN partial sums
__device__ float g_psq[128 * CC];                    // BN partial sum of squares
__device__ float g_stats[2 * CC];                    // per-channel scale / shift

// ---------------- K1: fused q/k/v 1x1 convs ----------------
__global__ void __launch_bounds__(128) k_qkv(
    const float* __restrict__ x,
    const float* __restrict__ Wq, const float* __restrict__ bq,
    const float* __restrict__ Wk, const float* __restrict__ bk,
    const float* __restrict__ Wv, const float* __restrict__ bv)
{
    __shared__ float WqS[CQ * CC], WkS[CQ * CC], WvS[CC * CC];
    __shared__ float bqS[CQ], bkS[CQ], bvS[CC];
    __shared__ float outS[128 * 17];

    const int t  = threadIdx.x;
    const int l0 = blockIdx.x * 128;
    const int b  = blockIdx.y;

    for (int e = t; e < CQ * CC; e += 128) { WqS[e] = Wq[e]; WkS[e] = Wk[e]; }
    for (int e = t; e < CC * CC; e += 128) WvS[e] = Wv[e];
    if (t < CQ) { bqS[t] = bq[t]; bkS[t] = bk[t]; }
    if (t < CC) bvS[t] = bv[t];
    __syncthreads();

    const float* xb = x + (size_t)b * CC * LL + l0 + t;

    for (int pass = 0; pass < 6; pass++) {
        const float* W;
        const float* bias;
        if (pass == 0)      { W = WqS; bias = bqS; }
        else if (pass == 1) { W = WkS; bias = bkS; }
        else                { W = WvS + (pass - 2) * 16 * CC; bias = bvS + (pass - 2) * 16; }

        float r[16];
        #pragma unroll
        for (int o = 0; o < 16; o++) r[o] = bias[o];

        for (int c = 0; c < CC; c++) {
            float xv = __ldg(xb + (size_t)c * LL);
            #pragma unroll
            for (int o = 0; o < 16; o++) r[o] += W[o * CC + c] * xv;
        }

        __syncthreads();
        #pragma unroll
        for (int o = 0; o < 16; o++) outS[t * 17 + o] = r[o];
        __syncthreads();

        if (pass == 0) {
            float* dst = g_qT + ((size_t)b * LL + l0) * CQ;
            for (int e = t; e < 128 * 16; e += 128) dst[e] = outS[(e >> 4) * 17 + (e & 15)];
        } else if (pass == 1) {
            float* dst = g_kT + ((size_t)b * LL + l0) * CQ;
            for (int e = t; e < 128 * 16; e += 128) dst[e] = outS[(e >> 4) * 17 + (e & 15)];
        } else {
            float* dst = g_vT + ((size_t)b * LL + l0) * CC + (pass - 2) * 16;
            for (int e = t; e < 128 * 16; e += 128) {
                int p = e >> 4, o = e & 15;
                dst[(size_t)p * CC + o] = outS[p * 17 + o];
            }
        }
    }
}

// ---------------- K2: deterministic stable counting sort per (b,h) ----------------
__global__ void __launch_bounds__(256) k_sort(const int* __restrict__ hash_idx)
{
    __shared__ int cnt[256 * 33];
    __shared__ int tot[NBK];
    __shared__ int bbase[NBK];

    const int t  = threadIdx.x;
    const int bh = blockIdx.x;
    const int* hp = hash_idx + (size_t)bh * LL;

    #pragma unroll
    for (int u = 0; u < 33; u++) cnt[t * 33 + u] = 0;

    const int l0 = t * 16;
    int loc[16];
    #pragma unroll
    for (int i = 0; i < 16; i++) {
        int bu = hp[l0 + i];
        loc[i] = bu;
        cnt[t * 33 + bu]++;
    }
    __syncthreads();

    if (t < NBK) {
        int run = 0;
        for (int j = 0; j < 256; j++) {
            int v = cnt[j * 33 + t];
            cnt[j * 33 + t] = run;
            run += v;
        }
        tot[t] = run;
    }
    __syncthreads();

    if (t == 0) {
        int running = 0;
        for (int u = 0; u < NBK; u++) {
            bbase[u] = running;
            g_boff[bh * (NBK + 1) + u] = running;
            running += tot[u];
        }
        g_boff[bh * (NBK + 1) + NBK] = running;
    }
    __syncthreads();

    int* sp = g_sidx + (size_t)bh * LL;
    #pragma unroll
    for (int i = 0; i < 16; i++) {
        int bu = loc[i];
        int pos = bbase[bu] + cnt[t * 33 + bu];
        cnt[t * 33 + bu]++;
        sp[pos] = l0 + i;
    }
}

// ---------------- K3: block-tiled per-bucket flash attention ----------------
// grid (NBK, NH, BB), block 256 = 8 warps.
// Warp w owns channels [w*8, w*8+8). Lane qg owns queries {qg, qg+32, qg+64, qg+96}.
// Per query-tile (<=128 queries): loop key-chunks of 32 with collective online softmax.
__global__ void __launch_bounds__(256) k_attn()
{
    __shared__ float Qs[128 * 17];   // [q][c], stride 17 -> conflict-free lane-adjacent reads
    __shared__ float Ks[32 * 17];    // [k][c]
    __shared__ float S[32 * 132];    // [k][q] scores -> probabilities
    __shared__ int   qposS[128];
    __shared__ int   kposS[32];
    __shared__ float mS[128], lS[128], corrS[128];

    const int bu = blockIdx.x, h = blockIdx.y, b = blockIdx.z;
    const int bh = b * NH + h;
    const int base = g_boff[bh * (NBK + 1) + bu];
    const int n    = g_boff[bh * (NBK + 1) + bu + 1] - base;
    if (n <= 0) return;

    const int*   sp  = g_sidx + (size_t)bh * LL + base;
    const float* kTb = g_kT + (size_t)b * LL * CQ;
    const float* qTb = g_qT + (size_t)b * LL * CQ;
    const float* vTb = g_vT + (size_t)b * LL * CC;
    float*       op  = g_accH + (size_t)bh * LL * CC;

    const int t = threadIdx.x, cg = t >> 5, lane = t & 31;

    for (int qt0 = 0; qt0 < n; qt0 += 128) {
        const int nq = min(128, n - qt0);

        __syncthreads();  // previous tile's smem readers done
        if (t < 128) {
            int q = min(t, nq - 1);
            qposS[t] = sp[qt0 + q];
            mS[t] = -3.0e38f;
            lS[t] = 0.f;
        }
        __syncthreads();
        for (int e = t; e < 128 * CQ; e += 256) {
            int q = e >> 4, c = e & 15;
            Qs[q * 17 + c] = qTb[(size_t)qposS[q] * CQ + c];
        }

        float acc[4][8];
        #pragma unroll
        for (int i = 0; i < 4; i++)
            #pragma unroll
            for (int j = 0; j < 8; j++) acc[i][j] = 0.f;

        for (int kt0 = 0; kt0 < n; kt0 += 32) {
            const int tn = min(32, n - kt0);
            __syncthreads();
            if (t < 32) kposS[t] = sp[kt0 + min(t, tn - 1)];
            __syncthreads();
            for (int e = t; e < 32 * CQ; e += 256) {
                int k = e >> 4, c = e & 15;
                Ks[k * 17 + c] = kTb[(size_t)kposS[k] * CQ + c];
            }
            __syncthreads();

            // GEMM1: warp cg computes score rows k = cg*4 .. cg*4+3
            {
                float s[4][4];
                #pragma unroll
                for (int j = 0; j < 4; j++)
                    #pragma unroll
                    for (int i = 0; i < 4; i++) s[j][i] = 0.f;

                #pragma unroll
                for (int c = 0; c < CQ; c++) {
                    float kv[4], qv[4];
                    #pragma unroll
                    for (int j = 0; j < 4; j++) kv[j] = Ks[(cg * 4 + j) * 17 + c];
                    #pragma unroll
                    for (int i = 0; i < 4; i++) qv[i] = Qs[(lane + 32 * i) * 17 + c];
                    #pragma unroll
                    for (int j = 0; j < 4; j++)
                        #pragma unroll
                        for (int i = 0; i < 4; i++) s[j][i] += kv[j] * qv[i];
                }
                #pragma unroll
                for (int j = 0; j < 4; j++) {
                    int k = cg * 4 + j;
                    bool valid = k < tn;
                    #pragma unroll
                    for (int i = 0; i < 4; i++)
                        S[k * 132 + lane + 32 * i] = valid ? s[j][i] : -3.0e38f;
                }
            }
            __syncthreads();

            // collective softmax: thread t<128 owns query t
            if (t < 128) {
                int q = t;
                float mold = mS[q];
                float cmax = -3.0e38f;
                #pragma unroll
                for (int k = 0; k < 32; k++) cmax = fmaxf(cmax, S[k * 132 + q]);
                float mnew = fmaxf(mold, cmax);
                float corr = __expf(mold - mnew);
                float ssum = 0.f;
                #pragma unroll
                for (int k = 0; k < 32; k++) {
                    float p = __expf(S[k * 132 + q] - mnew);
                    S[k * 132 + q] = p;
                    ssum += p;
                }
                lS[q] = lS[q] * corr + ssum;
                mS[q] = mnew;
                corrS[q] = corr;
            }
            __syncthreads();

            // rescale accumulators
            {
                float cr[4];
                #pragma unroll
                for (int i = 0; i < 4; i++) cr[i] = corrS[lane + 32 * i];
                #pragma unroll
                for (int i = 0; i < 4; i++)
                    #pragma unroll
                    for (int j = 0; j < 8; j++) acc[i][j] *= cr[i];
            }

            // PV: 32 independent accumulator chains, V via warp-uniform LDG.128
            #pragma unroll 4
            for (int k = 0; k < 32; k++) {
                float p0 = S[k * 132 + lane];
                float p1 = S[k * 132 + lane + 32];
                float p2 = S[k * 132 + lane + 64];
                float p3 = S[k * 132 + lane + 96];
                const float4* vp = (const float4*)(vTb + (size_t)kposS[k] * CC + cg * 8);
                float4 va = __ldg(vp);
                float4 vb = __ldg(vp + 1);
                acc[0][0] += p0 * va.x; acc[0][1] += p0 * va.y; acc[0][2] += p0 * va.z; acc[0][3] += p0 * va.w;
                acc[0][4] += p0 * vb.x; acc[0][5] += p0 * vb.y; acc[0][6] += p0 * vb.z; acc[0][7] += p0 * vb.w;
                acc[1][0] += p1 * va.x; acc[1][1] += p1 * va.y; acc[1][2] += p1 * va.z; acc[1][3] += p1 * va.w;
                acc[1][4] += p1 * vb.x; acc[1][5] += p1 * vb.y; acc[1][6] += p1 * vb.z; acc[1][7] += p1 * vb.w;
                acc[2][0] += p2 * va.x; acc[2][1] += p2 * va.y; acc[2][2] += p2 * va.z; acc[2][3] += p2 * va.w;
                acc[2][4] += p2 * vb.x; acc[2][5] += p2 * vb.y; acc[2][6] += p2 * vb.z; acc[2][7] += p2 * vb.w;
                acc[3][0] += p3 * va.x; acc[3][1] += p3 * va.y; acc[3][2] += p3 * va.z; acc[3][3] += p3 * va.w;
                acc[3][4] += p3 * vb.x; acc[3][5] += p3 * vb.y; acc[3][6] += p3 * vb.z; acc[3][7] += p3 * vb.w;
            }
        }

        // write this query-tile's output
        __syncthreads();
        #pragma unroll
        for (int i = 0; i < 4; i++) {
            int q = lane + 32 * i;
            if (q < nq) {
                float inv = 1.0f / lS[q];
                float* dst = op + (size_t)qposS[q] * CC + cg * 8;
                float4 o0 = make_float4(acc[i][0] * inv, acc[i][1] * inv, acc[i][2] * inv, acc[i][3] * inv);
                float4 o1 = make_float4(acc[i][4] * inv, acc[i][5] * inv, acc[i][6] * inv, acc[i][7] * inv);
                *(float4*)dst = o0;
                *(float4*)(dst + 4) = o1;
            }
        }
    }
}

// ---------------- K4: hash-average + Wo conv + residual + BN partials ----------------
__global__ void __launch_bounds__(512) k_out(
    const float* __restrict__ x,
    const float* __restrict__ Wo, const float* __restrict__ bo,
    const float* __restrict__ gamma, float* __restrict__ out)
{
    extern __shared__ float sm[];
    float* WoS   = sm;          // 64*64
    float* attnS = sm + 4096;   // [c][pos], stride 132

    const int t  = threadIdx.x;
    const int l0 = blockIdx.x * 128;
    const int b  = blockIdx.y;

    for (int e = t; e < CC * CC; e += 512) WoS[e] = Wo[e];

    const float* ab = g_accH + (size_t)b * NH * LL * CC + (size_t)l0 * CC;
    const size_t hstr = (size_t)LL * CC;
    for (int e = t; e < 128 * CC; e += 512) {
        int pos = e >> 6, c = e & 63;
        size_t off = (size_t)pos * CC + c;
        float s = ab[off] + ab[off + hstr] + ab[off + 2 * hstr] + ab[off + 3 * hstr];
        attnS[c * 132 + pos] = 0.25f * s;
    }
    __syncthreads();

    const int ct = t >> 5, pt = t & 31, c0 = ct * 4;
    float acc[4][4];
    #pragma unroll
    for (int i = 0; i < 4; i++) {
        float bi = __ldg(bo + c0 + i);
        #pragma unroll
        for (int j = 0; j < 4; j++) acc[i][j] = bi;
    }

    for (int cp = 0; cp < CC; cp++) {
        float4 av = *(const float4*)&attnS[cp * 132 + pt * 4];
        #pragma unroll
        for (int i = 0; i < 4; i++) {
            float w = WoS[(c0 + i) * CC + cp];
            acc[i][0] += w * av.x; acc[i][1] += w * av.y;
            acc[i][2] += w * av.z; acc[i][3] += w * av.w;
        }
    }

    const float g = __ldg(gamma);
    const int blk = b * gridDim.x + blockIdx.x;

    #pragma unroll
    for (int i = 0; i < 4; i++) {
        int c = c0 + i;
        size_t gbase = ((size_t)b * CC + c) * LL + l0 + pt * 4;
        float4 xv = *(const float4*)(x + gbase);
        float4 y;
        y.x = g * acc[i][0] + xv.x;
        y.y = g * acc[i][1] + xv.y;
        y.z = g * acc[i][2] + xv.z;
        y.w = g * acc[i][3] + xv.w;
        *(float4*)(out + gbase) = y;

        float s1 = y.x + y.y + y.z + y.w;
        float s2 = y.x * y.x + y.y * y.y + y.z * y.z + y.w * y.w;
        #pragma unroll
        for (int o = 16; o; o >>= 1) {
            s1 += __shfl_xor_sync(0xffffffffu, s1, o);
            s2 += __shfl_xor_sync(0xffffffffu, s2, o);
        }
        if (pt == 0) { g_part[blk * CC + c] = s1; g_psq[blk * CC + c] = s2; }
    }
}

// ---------------- K5: BN stats reduce ----------------
__global__ void k_stats(const float* __restrict__ bn_w, const float* __restrict__ bn_b)
{
    int c = threadIdx.x;
    double s1 = 0.0, s2 = 0.0;
    for (int i = 0; i < 128; i++) { s1 += g_part[i * CC + c]; s2 += g_psq[i * CC + c]; }
    const double n = (double)BB * (double)LL;
    double mean = s1 / n;
    double var  = s2 / n - mean * mean;
    double a    = (double)bn_w[c] / sqrt(var + 1e-5);
    g_stats[c]      = (float)a;
    g_stats[CC + c] = (float)((double)bn_b[c] - mean * a);
}

// ---------------- K6: normalize in place ----------------
__global__ void __launch_bounds__(256) k_norm(float* __restrict__ out)
{
    int i = blockIdx.x * 256 + threadIdx.x;
    int c = (i >> 10) & 63;
    float a = g_stats[c], sh = g_stats[CC + c];
    float4* p = (float4*)out;
    float4 v = p[i];
    v.x = v.x * a + sh; v.y = v.y * a + sh;
    v.z = v.z * a + sh; v.w = v.w * a + sh;
    p[i] = v;
}

// ---------------- launch ----------------
extern "C" void kernel_launch(void* const* d_in, const int* in_sizes, int n_in,
                              void* d_out, int out_size)
{
    const float* x     = (const float*)d_in[0];
    const int*   hashi = (const int*)  d_in[1];
    const float* Wq    = (const float*)d_in[2];
    const float* bq    = (const float*)d_in[3];
    const float* Wk    = (const float*)d_in[4];
    const float* bk    = (const float*)d_in[5];
    const float* Wv    = (const float*)d_in[6];
    const float* bv    = (const float*)d_in[7];
    const float* Wo    = (const float*)d_in[8];
    const float* bo    = (const float*)d_in[9];
    const float* gamma = (const float*)d_in[10];
    const float* bn_w  = (const float*)d_in[11];
    const float* bn_b  = (const float*)d_in[12];
    float* out = (float*)d_out;

    cudaFuncSetAttribute(k_out, cudaFuncAttributeMaxDynamicSharedMemorySize, 65536);

    k_qkv<<<dim3(LL / 128, BB), 128>>>(x, Wq, bq, Wk, bk, Wv, bv);
    k_sort<<<BB * NH, 256>>>(hashi);
    k_attn<<<dim3(NBK, NH, BB), 256>>>();
    k_out<<<dim3(LL / 128, BB), 512, 50176>>>(x, Wo, bo, gamma, out);
    k_stats<<<1, 64>>>(bn_w, bn_b);
    k_norm<<<(BB * CC * LL / 4) / 256, 256>>>(out);
}

// round 7
// speedup vs baseline: 3.1291x; 1.3689x over previous
#include <cuda_runtime.h>
#include <math.h>

#define BB 4
#define CC 64
#define LL 4096
#define CQ 16
#define NH 4
#define NBK 32
#define NITEMS (BB * NH * NBK * 2)   // 1024 work items: (b,h,bucket,q-half)

typedef unsigned long long ull;

// ---------------- scratch (device globals; no allocation allowed) ----------------
__device__ float g_qT[BB * LL * CQ];                 // (b, l, cq)
__device__ float g_kT[BB * LL * CQ];                 // (b, l, cq)
__device__ float g_vT[BB * LL * CC];                 // (b, l, c)
__device__ int   g_sidx[BB * NH * LL];               // sorted member lists per (b,h)
__device__ int   g_boff[BB * NH * (NBK + 1)];        // bucket offsets per (b,h)
__device__ float g_accH[(size_t)BB * NH * LL * CC];  // per-hash attention output (b,h,l,c)
__device__ float g_part[256 * CC];                   // BN partial sums
__device__ float g_psq[256 * CC];                    // BN partial sum of squares
__device__ float g_stats[2 * CC];                    // per-channel scale / shift
__device__ int   g_work;                             // dynamic work counter

// ---------------- packed f32x2 helpers ----------------
__device__ __forceinline__ ull pk2(float x) {
    ull r; asm("mov.b64 %0, {%1, %1};" : "=l"(r) : "f"(x)); return r;
}
__device__ __forceinline__ ull pk(float lo, float hi) {
    ull r; asm("mov.b64 %0, {%1, %2};" : "=l"(r) : "f"(lo), "f"(hi)); return r;
}
__device__ __forceinline__ float2 upk(ull a) {
    float2 f; asm("mov.b64 {%0, %1}, %2;" : "=f"(f.x), "=f"(f.y) : "l"(a)); return f;
}
__device__ __forceinline__ ull ff2(ull a, ull b, ull c) {
    ull d; asm("fma.rn.f32x2 %0, %1, %2, %3;" : "=l"(d) : "l"(a), "l"(b), "l"(c)); return d;
}
__device__ __forceinline__ ull mul2(ull a, ull b) {
    ull d; asm("mul.rn.f32x2 %0, %1, %2;" : "=l"(d) : "l"(a), "l"(b)); return d;
}

// ---------------- K1: q/k/v 1x1 convs, split by output pass ----------------
// grid (LL/128, BB, 6), block 128
__global__ void __launch_bounds__(128) k_qkv(
    const float* __restrict__ x,
    const float* __restrict__ Wq, const float* __restrict__ bq,
    const float* __restrict__ Wk, const float* __restrict__ bk,
    const float* __restrict__ Wv, const float* __restrict__ bv)
{
    __shared__ float WS[CQ * CC];
    __shared__ float bS[CQ];
    __shared__ float outS[128 * 17];

    const int t = threadIdx.x;
    const int l0 = blockIdx.x * 128;
    const int b  = blockIdx.y;
    const int pass = blockIdx.z;

    const float* Wsrc; const float* bsrc;
    if (pass == 0)      { Wsrc = Wq; bsrc = bq; }
    else if (pass == 1) { Wsrc = Wk; bsrc = bk; }
    else                { Wsrc = Wv + (pass - 2) * CQ * CC; bsrc = bv + (pass - 2) * CQ; }

    for (int e = t; e < CQ * CC; e += 128) WS[e] = Wsrc[e];
    if (t < CQ) bS[t] = bsrc[t];
    __syncthreads();

    const float* xb = x + (size_t)b * CC * LL + l0 + t;

    float r[16];
    #pragma unroll
    for (int o = 0; o < 16; o++) r[o] = bS[o];

    for (int c = 0; c < CC; c++) {
        float xv = __ldg(xb + (size_t)c * LL);
        #pragma unroll
        for (int o = 0; o < 16; o++) r[o] += WS[o * CC + c] * xv;
    }

    #pragma unroll
    for (int o = 0; o < 16; o++) outS[t * 17 + o] = r[o];
    __syncthreads();

    if (pass == 0) {
        float* dst = g_qT + ((size_t)b * LL + l0) * CQ;
        for (int e = t; e < 128 * 16; e += 128) dst[e] = outS[(e >> 4) * 17 + (e & 15)];
    } else if (pass == 1) {
        float* dst = g_kT + ((size_t)b * LL + l0) * CQ;
        for (int e = t; e < 128 * 16; e += 128) dst[e] = outS[(e >> 4) * 17 + (e & 15)];
    } else {
        float* dst = g_vT + ((size_t)b * LL + l0) * CC + (pass - 2) * 16;
        for (int e = t; e < 128 * 16; e += 128) {
            int p = e >> 4, o = e & 15;
            dst[(size_t)p * CC + o] = outS[p * 17 + o];
        }
    }
}

// ---------------- K2: deterministic stable counting sort per (b,h) ----------------
__global__ void __launch_bounds__(256) k_sort(const int* __restrict__ hash_idx)
{
    __shared__ int cnt[256 * 33];
    __shared__ int tot[NBK];
    __shared__ int bbase[NBK];

    const int t  = threadIdx.x;
    const int bh = blockIdx.x;
    if (bh == 0 && t == 0) g_work = 0;   // reset attention work queue each launch
    const int* hp = hash_idx + (size_t)bh * LL;

    #pragma unroll
    for (int u = 0; u < 33; u++) cnt[t * 33 + u] = 0;

    const int l0 = t * 16;
    int loc[16];
    #pragma unroll
    for (int i = 0; i < 16; i++) {
        int bu = hp[l0 + i];
        loc[i] = bu;
        cnt[t * 33 + bu]++;
    }
    __syncthreads();

    if (t < NBK) {
        int run = 0;
        for (int j = 0; j < 256; j++) {
            int v = cnt[j * 33 + t];
            cnt[j * 33 + t] = run;
            run += v;
        }
        tot[t] = run;
    }
    __syncthreads();

    if (t == 0) {
        int running = 0;
        for (int u = 0; u < NBK; u++) {
            bbase[u] = running;
            g_boff[bh * (NBK + 1) + u] = running;
            running += tot[u];
        }
        g_boff[bh * (NBK + 1) + NBK] = running;
    }
    __syncthreads();

    int* sp = g_sidx + (size_t)bh * LL;
    #pragma unroll
    for (int i = 0; i < 16; i++) {
        int bu = loc[i];
        int pos = bbase[bu] + cnt[t * 33 + bu];
        cnt[t * 33 + bu]++;
        sp[pos] = l0 + i;
    }
}

// ---------------- K3: persistent per-bucket flash attention ----------------
// 444 persistent blocks of 256 threads pull (b,h,bucket,q-half) items.
// Per item: <=64-query subtiles, key chunks of 64, parallel online softmax,
// packed f32x2 FMA in both GEMMs.
__global__ void __launch_bounds__(256) k_attn()
{
    __shared__ __align__(16) float Qs[CQ * 68];   // [c][q]
    __shared__ __align__(16) float Ks[CQ * 68];   // [c][k]
    __shared__ __align__(16) float Vs[64 * 68];   // [k][c]
    __shared__ __align__(16) float S[64 * 68];    // [q][k]
    __shared__ float Pm[4 * 68], Ps[4 * 68];
    __shared__ float mS[2][64], lS[64], corrS[64];
    __shared__ int itemS;

    const int t = threadIdx.x, w = t >> 5, lane = t & 31;
    const int qa = t & 63, seg = t >> 6;

    for (;;) {
        if (t == 0) itemS = atomicAdd(&g_work, 1);
        __syncthreads();
        const int item = itemS;
        if (item >= NITEMS) break;

        const int qh = item & 1;
        const int bu = (item >> 1) & (NBK - 1);
        const int bh = item >> 6;
        const int b  = bh >> 2;

        const int base = g_boff[bh * (NBK + 1) + bu];
        const int n    = g_boff[bh * (NBK + 1) + bu + 1] - base;
        const int h0   = qh * ((n + 1) >> 1);
        const int nqt  = (qh == 0) ? ((n + 1) >> 1) : (n - ((n + 1) >> 1));
        if (n <= 0 || nqt <= 0) { __syncthreads(); continue; }

        const int*   sp  = g_sidx + (size_t)bh * LL + base;
        const float* kTb = g_kT + (size_t)b * LL * CQ;
        const float* qTb = g_qT + (size_t)b * LL * CQ;
        const float* vTb = g_vT + (size_t)b * LL * CC;
        float*       op  = g_accH + (size_t)bh * LL * CC;

        for (int q0 = h0; q0 < h0 + nqt; q0 += 64) {
            const int nq = min(64, h0 + nqt - q0);

            // init state + stage Q (64 rows) into [c][q]
            if (t < 64) {
                mS[0][t] = -3.0e38f;
                lS[t] = 0.f;
                int qp = sp[q0 + min(t, nq - 1)];
                const float4* qr = (const float4*)(qTb + (size_t)qp * CQ);
                #pragma unroll
                for (int c4 = 0; c4 < 4; c4++) {
                    float4 v = __ldg(qr + c4);
                    Qs[(c4 * 4 + 0) * 68 + t] = v.x;
                    Qs[(c4 * 4 + 1) * 68 + t] = v.y;
                    Qs[(c4 * 4 + 2) * 68 + t] = v.z;
                    Qs[(c4 * 4 + 3) * 68 + t] = v.w;
                }
            }

            ull A0[4] = {0, 0, 0, 0}, A1[4] = {0, 0, 0, 0};
            int par = 0;

            for (int k0 = 0; k0 < n; k0 += 64) {
                const int tn = min(64, n - k0);
                __syncthreads();  // prev chunk consumers done; Qs ready (1st iter)

                // stage K [c][k]
                if (t < 64) {
                    int kp = __ldg(&sp[k0 + min(t, tn - 1)]);
                    const float4* kr = (const float4*)(kTb + (size_t)kp * CQ);
                    #pragma unroll
                    for (int c4 = 0; c4 < 4; c4++) {
                        float4 v = __ldg(kr + c4);
                        Ks[(c4 * 4 + 0) * 68 + t] = v.x;
                        Ks[(c4 * 4 + 1) * 68 + t] = v.y;
                        Ks[(c4 * 4 + 2) * 68 + t] = v.z;
                        Ks[(c4 * 4 + 3) * 68 + t] = v.w;
                    }
                }
                // stage V [k][c] cooperatively
                #pragma unroll
                for (int it = 0; it < 4; it++) {
                    int idx = t + it * 256;
                    int kk = idx >> 4, c4 = idx & 15;
                    int kp = __ldg(&sp[k0 + min(kk, tn - 1)]);
                    float4 v = __ldg((const float4*)(vTb + (size_t)kp * CC) + c4);
                    *(float4*)&Vs[kk * 68 + c4 * 4] = v;
                }
                __syncthreads();  // K/V staged

                // GEMM1: warp w -> k rows [w*8, w*8+8), packed over k-pairs
                {
                    ull s2[4][2] = {{0,0},{0,0},{0,0},{0,0}};
                    #pragma unroll
                    for (int c = 0; c < CQ; c++) {
                        ulonglong2 ka = *(const ulonglong2*)&Ks[c * 68 + w * 8];
                        ulonglong2 kb = *(const ulonglong2*)&Ks[c * 68 + w * 8 + 4];
                        ull qv0 = pk2(Qs[c * 68 + lane]);
                        ull qv1 = pk2(Qs[c * 68 + lane + 32]);
                        s2[0][0] = ff2(ka.x, qv0, s2[0][0]); s2[0][1] = ff2(ka.x, qv1, s2[0][1]);
                        s2[1][0] = ff2(ka.y, qv0, s2[1][0]); s2[1][1] = ff2(ka.y, qv1, s2[1][1]);
                        s2[2][0] = ff2(kb.x, qv0, s2[2][0]); s2[2][1] = ff2(kb.x, qv1, s2[2][1]);
                        s2[3][0] = ff2(kb.y, qv0, s2[3][0]); s2[3][1] = ff2(kb.y, qv1, s2[3][1]);
                    }
                    #pragma unroll
                    for (int j = 0; j < 4; j++) {
                        int k = w * 8 + 2 * j;
                        #pragma unroll
                        for (int i = 0; i < 2; i++) {
                            float2 v = upk(s2[j][i]);
                            float lo = (k     < tn) ? v.x : -3.0e38f;
                            float hi = (k + 1 < tn) ? v.y : -3.0e38f;
                            *(ull*)&S[(lane + 32 * i) * 68 + k] = pk(lo, hi);
                        }
                    }
                }
                __syncthreads();  // scores ready

                // softmax phase A: per-thread partial max over 16 keys (kept in regs)
                float4 r0, r1, r2, r3;
                {
                    const float* Sq = S + qa * 68 + seg * 16;
                    r0 = *(const float4*)(Sq);
                    r1 = *(const float4*)(Sq + 4);
                    r2 = *(const float4*)(Sq + 8);
                    r3 = *(const float4*)(Sq + 12);
                    float m = fmaxf(fmaxf(fmaxf(r0.x, r0.y), fmaxf(r0.z, r0.w)),
                                    fmaxf(fmaxf(r1.x, r1.y), fmaxf(r1.z, r1.w)));
                    m = fmaxf(m, fmaxf(fmaxf(fmaxf(r2.x, r2.y), fmaxf(r2.z, r2.w)),
                                       fmaxf(fmaxf(r3.x, r3.y), fmaxf(r3.z, r3.w))));
                    Pm[seg * 68 + qa] = m;
                }
                __syncthreads();

                // softmax phase B: exp + partial sums (all 256 threads)
                {
                    float mold = mS[par][qa];
                    float m4 = fmaxf(fmaxf(Pm[qa], Pm[68 + qa]), fmaxf(Pm[136 + qa], Pm[204 + qa]));
                    float mnew = fmaxf(mold, m4);
                    r0.x = __expf(r0.x - mnew); r0.y = __expf(r0.y - mnew);
                    r0.z = __expf(r0.z - mnew); r0.w = __expf(r0.w - mnew);
                    r1.x = __expf(r1.x - mnew); r1.y = __expf(r1.y - mnew);
                    r1.z = __expf(r1.z - mnew); r1.w = __expf(r1.w - mnew);
                    r2.x = __expf(r2.x - mnew); r2.y = __expf(r2.y - mnew);
                    r2.z = __expf(r2.z - mnew); r2.w = __expf(r2.w - mnew);
                    r3.x = __expf(r3.x - mnew); r3.y = __expf(r3.y - mnew);
                    r3.z = __expf(r3.z - mnew); r3.w = __expf(r3.w - mnew);
                    float* Sq = S + qa * 68 + seg * 16;
                    *(float4*)(Sq)      = r0;
                    *(float4*)(Sq + 4)  = r1;
                    *(float4*)(Sq + 8)  = r2;
                    *(float4*)(Sq + 12) = r3;
                    float ssum = ((r0.x + r0.y) + (r0.z + r0.w)) + ((r1.x + r1.y) + (r1.z + r1.w))
                               + ((r2.x + r2.y) + (r2.z + r2.w)) + ((r3.x + r3.y) + (r3.z + r3.w));
                    Ps[seg * 68 + qa] = ssum;
                    if (seg == 0) {
                        corrS[qa] = __expf(mold - mnew);
                        mS[par ^ 1][qa] = mnew;
                    }
                }
                __syncthreads();  // probs + corr ready

                // phase C: running denominator + PV (packed)
                if (t < 64)
                    lS[t] = lS[t] * corrS[t] + ((Ps[t] + Ps[68 + t]) + (Ps[136 + t] + Ps[204 + t]));
                {
                    ull C0 = pk2(corrS[lane]), C1 = pk2(corrS[lane + 32]);
                    #pragma unroll
                    for (int j = 0; j < 4; j++) { A0[j] = mul2(A0[j], C0); A1[j] = mul2(A1[j], C1); }

                    const float* S0 = S + lane * 68;
                    const float* S1 = S + (lane + 32) * 68;
                    #pragma unroll 4
                    for (int k4 = 0; k4 < 16; k4++) {
                        float4 p0 = *(const float4*)(S0 + k4 * 4);
                        float4 p1 = *(const float4*)(S1 + k4 * 4);
                        const float* vr = Vs + (k4 * 4) * 68 + w * 8;
                        #pragma unroll
                        for (int u = 0; u < 4; u++) {
                            ulonglong2 va = *(const ulonglong2*)(vr);
                            ulonglong2 vb = *(const ulonglong2*)(vr + 4);
                            float p0c = (u == 0) ? p0.x : (u == 1) ? p0.y : (u == 2) ? p0.z : p0.w;
                            float p1c = (u == 0) ? p1.x : (u == 1) ? p1.y : (u == 2) ? p1.z : p1.w;
                            ull P0 = pk2(p0c), P1 = pk2(p1c);
                            A0[0] = ff2(P0, va.x, A0[0]); A0[1] = ff2(P0, va.y, A0[1]);
                            A0[2] = ff2(P0, vb.x, A0[2]); A0[3] = ff2(P0, vb.y, A0[3]);
                            A1[0] = ff2(P1, va.x, A1[0]); A1[1] = ff2(P1, va.y, A1[1]);
                            A1[2] = ff2(P1, vb.x, A1[2]); A1[3] = ff2(P1, vb.y, A1[3]);
                            vr += 68;
                        }
                    }
                }
                par ^= 1;
            }

            __syncthreads();  // lS final

            // epilogue: write normalized outputs
            {
                ull INV0 = pk2(1.0f / lS[lane]);
                ull INV1 = pk2(1.0f / lS[lane + 32]);
                if (lane < nq) {
                    int qpos = __ldg(&sp[q0 + lane]);
                    float* dst = op + (size_t)qpos * CC + w * 8;
                    ulonglong2 o;
                    o.x = mul2(A0[0], INV0); o.y = mul2(A0[1], INV0);
                    *(ulonglong2*)dst = o;
                    o.x = mul2(A0[2], INV0); o.y = mul2(A0[3], INV0);
                    *(ulonglong2*)(dst + 4) = o;
                }
                if (lane + 32 < nq) {
                    int qpos = __ldg(&sp[q0 + lane + 32]);
                    float* dst = op + (size_t)qpos * CC + w * 8;
                    ulonglong2 o;
                    o.x = mul2(A1[0], INV1); o.y = mul2(A1[1], INV1);
                    *(ulonglong2*)dst = o;
                    o.x = mul2(A1[2], INV1); o.y = mul2(A1[3], INV1);
                    *(ulonglong2*)(dst + 4) = o;
                }
            }
            __syncthreads();  // smem reusable for next subtile / item
        }
    }
}

// ---------------- K4: hash-average + Wo conv + residual + BN partials ----------------
// grid (LL/64, BB) = 256 blocks, 256 threads: 64 pos x 64 ch tiles
__global__ void __launch_bounds__(256) k_out(
    const float* __restrict__ x,
    const float* __restrict__ Wo, const float* __restrict__ bo,
    const float* __restrict__ gamma, float* __restrict__ out)
{
    __shared__ float WoS[CC * 65];
    __shared__ __align__(16) float attnS[CC * 68];   // [c][pos]

    const int t  = threadIdx.x;
    const int l0 = blockIdx.x * 64;
    const int b  = blockIdx.y;

    for (int e = t; e < CC * CC; e += 256) WoS[(e >> 6) * 65 + (e & 63)] = Wo[e];

    const float* ab = g_accH + (size_t)b * NH * LL * CC + (size_t)l0 * CC;
    const size_t hstr = (size_t)LL * CC;
    for (int e = t; e < 64 * CC; e += 256) {
        int pos = e >> 6, c = e & 63;
        size_t off = (size_t)pos * CC + c;
        float s = ab[off] + ab[off + hstr] + ab[off + 2 * hstr] + ab[off + 3 * hstr];
        attnS[c * 68 + pos] = 0.25f * s;
    }
    __syncthreads();

    const int cgrp = t >> 4, pgrp = t & 15, c0 = cgrp * 4;
    float acc[4][4];
    #pragma unroll
    for (int i = 0; i < 4; i++) {
        float bi = __ldg(bo + c0 + i);
        #pragma unroll
        for (int j = 0; j < 4; j++) acc[i][j] = bi;
    }

    for (int cp = 0; cp < CC; cp++) {
        float4 av = *(const float4*)&attnS[cp * 68 + pgrp * 4];
        #pragma unroll
        for (int i = 0; i < 4; i++) {
            float w = WoS[(c0 + i) * 65 + cp];
            acc[i][0] += w * av.x; acc[i][1] += w * av.y;
            acc[i][2] += w * av.z; acc[i][3] += w * av.w;
        }
    }

    const float g = __ldg(gamma);
    const int blk = b * gridDim.x + blockIdx.x;   // 0..255

    #pragma unroll
    for (int i = 0; i < 4; i++) {
        int c = c0 + i;
        size_t gbase = ((size_t)b * CC + c) * LL + l0 + pgrp * 4;
        float4 xv = *(const float4*)(x + gbase);
        float4 y;
        y.x = g * acc[i][0] + xv.x;
        y.y = g * acc[i][1] + xv.y;
        y.z = g * acc[i][2] + xv.z;
        y.w = g * acc[i][3] + xv.w;
        *(float4*)(out + gbase) = y;

        float s1 = y.x + y.y + y.z + y.w;
        float s2 = y.x * y.x + y.y * y.y + y.z * y.z + y.w * y.w;
        #pragma unroll
        for (int o = 8; o; o >>= 1) {          // reduce within 16-lane pgrp group
            s1 += __shfl_xor_sync(0xffffffffu, s1, o);
            s2 += __shfl_xor_sync(0xffffffffu, s2, o);
        }
        if (pgrp == 0) { g_part[blk * CC + c] = s1; g_psq[blk * CC + c] = s2; }
    }
}

// ---------------- K5: BN stats reduce (256 threads) ----------------
__global__ void __launch_bounds__(256) k_stats(const float* __restrict__ bn_w, const float* __restrict__ bn_b)
{
    __shared__ double sd1[256], sd2[256];
    const int t = threadIdx.x;
    const int c = t & 63, qr = t >> 6;
    double s1 = 0.0, s2 = 0.0;
    for (int i = qr * 64; i < qr * 64 + 64; i++) {
        s1 += g_part[i * CC + c];
        s2 += g_psq[i * CC + c];
    }
    sd1[t] = s1; sd2[t] = s2;
    __syncthreads();
    if (t < 64) {
        double t1 = sd1[t] + sd1[64 + t] + sd1[128 + t] + sd1[192 + t];
        double t2 = sd2[t] + sd2[64 + t] + sd2[128 + t] + sd2[192 + t];
        const double n = (double)BB * (double)LL;
        double mean = t1 / n;
        double var  = t2 / n - mean * mean;
        double a    = (double)bn_w[t] / sqrt(var + 1e-5);
        g_stats[t]      = (float)a;
        g_stats[CC + t] = (float)((double)bn_b[t] - mean * a);
    }
}

// ---------------- K6: normalize in place ----------------
__global__ void __launch_bounds__(256) k_norm(float* __restrict__ out)
{
    int i = blockIdx.x * 256 + threadIdx.x;
    int c = (i >> 10) & 63;
    float a = g_stats[c], sh = g_stats[CC + c];
    float4* p = (float4*)out;
    float4 v = p[i];
    v.x = v.x * a + sh; v.y = v.y * a + sh;
    v.z = v.z * a + sh; v.w = v.w * a + sh;
    p[i] = v;
}

// ---------------- launch ----------------
extern "C" void kernel_launch(void* const* d_in, const int* in_sizes, int n_in,
                              void* d_out, int out_size)
{
    const float* x     = (const float*)d_in[0];
    const int*   hashi = (const int*)  d_in[1];
    const float* Wq    = (const float*)d_in[2];
    const float* bq    = (const float*)d_in[3];
    const float* Wk    = (const float*)d_in[4];
    const float* bk    = (const float*)d_in[5];
    const float* Wv    = (const float*)d_in[6];
    const float* bv    = (const float*)d_in[7];
    const float* Wo    = (const float*)d_in[8];
    const float* bo    = (const float*)d_in[9];
    const float* gamma = (const float*)d_in[10];
    const float* bn_w  = (const float*)d_in[11];
    const float* bn_b  = (const float*)d_in[12];
    float* out = (float*)d_out;

    k_qkv<<<dim3(LL / 128, BB, 6), 128>>>(x, Wq, bq, Wk, bk, Wv, bv);
    k_sort<<<BB * NH, 256>>>(hashi);
    k_attn<<<444, 256>>>();
    k_out<<<dim3(LL / 64, BB), 256>>>(x, Wo, bo, gamma, out);
    k_stats<<<1, 256>>>(bn_w, bn_b);
    k_norm<<<(BB * CC * LL / 4) / 256, 256>>>(out);
}